// round 1
// baseline (speedup 1.0000x reference)
#include <cuda_runtime.h>
#include <math.h>

// Problem constants (fixed by the dataset)
#define D_MODEL 1024
#define NHEADS  16
#define DHEAD   64          // D_MODEL / NHEADS
#define BATCH   4
#define SEQ     2048
#define MROWS   (BATCH * SEQ)   // 8192 rows for all GEMMs

// ---------------------------------------------------------------------------
// Scratch (no cudaMalloc allowed): 4 x 32 MB fp32 buffers as __device__ globals
// ---------------------------------------------------------------------------
__device__ float g_q[MROWS * D_MODEL];
__device__ float g_k[MROWS * D_MODEL];
__device__ float g_v[MROWS * D_MODEL];
__device__ float g_att[MROWS * D_MODEL];

// ---------------------------------------------------------------------------
// SGEMM: C[M,N] = A[M,K] @ W[K,N] + bias[N]     (all row-major, fp32)
// Block tile 128x128, K-tile 8, 256 threads, 8x8 register tile per thread.
// M=8192, N=1024, K=1024 are exact multiples of the tiles -> no bounds checks.
// ---------------------------------------------------------------------------
#define BM 128
#define BN 128
#define BK 8
#define TM 8
#define TN 8

__global__ __launch_bounds__(256, 2)
void sgemm_bias_kernel(const float* __restrict__ A,
                       const float* __restrict__ W,
                       const float* __restrict__ bias,
                       float* __restrict__ C,
                       int M, int N, int K)
{
    __shared__ float As[BK][BM];   // transposed A tile: As[k][m]
    __shared__ float Bs[BK][BN];

    const int tid = threadIdx.x;
    const int bx  = blockIdx.x;    // tile along N
    const int by  = blockIdx.y;    // tile along M

    const float* Ablk = A + (size_t)by * BM * K;
    const float* Wblk = W + (size_t)bx * BN;

    // A tile load: 128x8 floats = 1024 = 256 threads * 1 float4
    const int arow = tid >> 1;            // 0..127
    const int acol = (tid & 1) * 4;       // 0 or 4
    // B tile load: 8x128 floats = 1024 = 256 threads * 1 float4
    const int brow = tid >> 5;            // 0..7
    const int bcol = (tid & 31) * 4;      // 0..124

    const int tx = tid & 15;              // 0..15 -> col group
    const int ty = tid >> 4;              // 0..15 -> row group

    float acc[TM][TN];
#pragma unroll
    for (int i = 0; i < TM; ++i)
#pragma unroll
        for (int j = 0; j < TN; ++j)
            acc[i][j] = 0.0f;

    for (int k0 = 0; k0 < K; k0 += BK) {
        float4 a4 = *(const float4*)(Ablk + (size_t)arow * K + k0 + acol);
        As[acol + 0][arow] = a4.x;
        As[acol + 1][arow] = a4.y;
        As[acol + 2][arow] = a4.z;
        As[acol + 3][arow] = a4.w;

        float4 b4 = *(const float4*)(Wblk + (size_t)(k0 + brow) * N + bcol);
        *(float4*)&Bs[brow][bcol] = b4;

        __syncthreads();

#pragma unroll
        for (int kk = 0; kk < BK; ++kk) {
            float am[TM], bn[TN];
            // 8 consecutive floats -> two float4 loads each (32B aligned rows)
            float4 am0 = *(const float4*)&As[kk][ty * TM + 0];
            float4 am1 = *(const float4*)&As[kk][ty * TM + 4];
            am[0]=am0.x; am[1]=am0.y; am[2]=am0.z; am[3]=am0.w;
            am[4]=am1.x; am[5]=am1.y; am[6]=am1.z; am[7]=am1.w;
            float4 bn0 = *(const float4*)&Bs[kk][tx * TN + 0];
            float4 bn1 = *(const float4*)&Bs[kk][tx * TN + 4];
            bn[0]=bn0.x; bn[1]=bn0.y; bn[2]=bn0.z; bn[3]=bn0.w;
            bn[4]=bn1.x; bn[5]=bn1.y; bn[6]=bn1.z; bn[7]=bn1.w;
#pragma unroll
            for (int i = 0; i < TM; ++i)
#pragma unroll
                for (int j = 0; j < TN; ++j)
                    acc[i][j] = fmaf(am[i], bn[j], acc[i][j]);
        }
        __syncthreads();
    }

    // Epilogue: add bias, write out (vectorized float4 per 4 cols)
#pragma unroll
    for (int i = 0; i < TM; ++i) {
        const int row = by * BM + ty * TM + i;
        float* crow = C + (size_t)row * N + bx * BN + tx * TN;
        const float* brow_p = bias + bx * BN + tx * TN;
        float4 o0, o1;
        o0.x = acc[i][0] + brow_p[0];
        o0.y = acc[i][1] + brow_p[1];
        o0.z = acc[i][2] + brow_p[2];
        o0.w = acc[i][3] + brow_p[3];
        o1.x = acc[i][4] + brow_p[4];
        o1.y = acc[i][5] + brow_p[5];
        o1.z = acc[i][6] + brow_p[6];
        o1.w = acc[i][7] + brow_p[7];
        *(float4*)(crow + 0) = o0;
        *(float4*)(crow + 4) = o1;
    }
}

// ---------------------------------------------------------------------------
// Dilated local attention, one warp per (b, h, q).
// allowed j = q + (t - k)*dilation, t in [0, 2k], 0 <= j < SEQ.
// Online softmax, 2 head-dims per lane (DHEAD=64).
// ---------------------------------------------------------------------------
__global__ __launch_bounds__(256)
void dilated_attn_kernel(const float* __restrict__ Q,
                         const float* __restrict__ Kb,
                         const float* __restrict__ V,
                         float* __restrict__ O,
                         const int* __restrict__ kptr,
                         const int* __restrict__ dptr)
{
    const int warp = (blockIdx.x * blockDim.x + threadIdx.x) >> 5;
    const int lane = threadIdx.x & 31;
    // warp id -> (b, h, q); q fastest for K/V cache locality
    const int q  = warp % SEQ;
    const int bh = warp / SEQ;
    const int h  = bh % NHEADS;
    const int b  = bh / NHEADS;

    const int kw  = *kptr;    // window half-count
    const int dil = *dptr;

    const size_t rowq = (size_t)(b * SEQ + q) * D_MODEL + h * DHEAD;
    const float q0 = Q[rowq + lane];
    const float q1 = Q[rowq + lane + 32];
    const float scale = rsqrtf((float)DHEAD);

    float m = -1e30f, l = 0.0f, a0 = 0.0f, a1 = 0.0f;

    const int tmax = 2 * kw;
    for (int t = 0; t <= tmax; ++t) {
        const int j = q + (t - kw) * dil;
        if (j < 0 || j >= SEQ) continue;
        const size_t rowj = (size_t)(b * SEQ + j) * D_MODEL + h * DHEAD;

        float p = q0 * Kb[rowj + lane] + q1 * Kb[rowj + lane + 32];
#pragma unroll
        for (int s = 16; s > 0; s >>= 1)
            p += __shfl_xor_sync(0xffffffffu, p, s);
        const float sc = p * scale;

        const float mn   = fmaxf(m, sc);
        const float corr = __expf(m - mn);   // 0 when m == -1e30
        const float e    = __expf(sc - mn);
        a0 = a0 * corr + e * V[rowj + lane];
        a1 = a1 * corr + e * V[rowj + lane + 32];
        l  = l * corr + e;
        m  = mn;
    }

    const float inv = 1.0f / l;   // offset 0 always allowed -> l > 0
    float* op = O + rowq;
    op[lane]      = a0 * inv;
    op[lane + 32] = a1 * inv;
}

// ---------------------------------------------------------------------------
// Launch
// ---------------------------------------------------------------------------
extern "C" void kernel_launch(void* const* d_in, const int* in_sizes, int n_in,
                              void* d_out, int out_size)
{
    const float* x  = (const float*)d_in[0];
    const float* Wq = (const float*)d_in[1];
    const float* bq = (const float*)d_in[2];
    const float* Wk = (const float*)d_in[3];
    const float* bk = (const float*)d_in[4];
    const float* Wv = (const float*)d_in[5];
    const float* bv = (const float*)d_in[6];
    const float* Wo = (const float*)d_in[7];
    const float* bo = (const float*)d_in[8];
    const int*   kp = (const int*)d_in[9];
    const int*   dp = (const int*)d_in[10];
    float* out = (float*)d_out;

    void *pq, *pk, *pv, *pa;
    cudaGetSymbolAddress(&pq, g_q);
    cudaGetSymbolAddress(&pk, g_k);
    cudaGetSymbolAddress(&pv, g_v);
    cudaGetSymbolAddress(&pa, g_att);
    float* qbuf = (float*)pq;
    float* kbuf = (float*)pk;
    float* vbuf = (float*)pv;
    float* abuf = (float*)pa;

    const dim3 gblk(256);
    const dim3 ggrd(D_MODEL / BN, MROWS / BM);   // (8, 64)

    // QKV projections
    sgemm_bias_kernel<<<ggrd, gblk>>>(x, Wq, bq, qbuf, MROWS, D_MODEL, D_MODEL);
    sgemm_bias_kernel<<<ggrd, gblk>>>(x, Wk, bk, kbuf, MROWS, D_MODEL, D_MODEL);
    sgemm_bias_kernel<<<ggrd, gblk>>>(x, Wv, bv, vbuf, MROWS, D_MODEL, D_MODEL);

    // Dilated attention: one warp per (b,h,q) => B*H*SEQ warps, 8 warps/block
    const int n_warps  = BATCH * NHEADS * SEQ;       // 131072
    const int n_blocks = n_warps / 8;                // 16384
    dilated_attn_kernel<<<n_blocks, 256>>>(qbuf, kbuf, vbuf, abuf, kp, dp);

    // Output projection -> d_out
    sgemm_bias_kernel<<<ggrd, gblk>>>(abuf, Wo, bo, out, MROWS, D_MODEL, D_MODEL);
}

// round 3
// speedup vs baseline: 2.4216x; 2.4216x over previous
#include <cuda_runtime.h>
#include <cuda_bf16.h>
#include <cstdint>
#include <math.h>

// Problem constants
#define D_MODEL 1024
#define NHEADS  16
#define DHEAD   64
#define BATCH   4
#define SEQ     2048
#define MROWS   (BATCH * SEQ)   // 8192

// ---------------------------------------------------------------------------
// Scratch (__device__ globals; no cudaMalloc allowed)
// ---------------------------------------------------------------------------
__device__ float g_q[MROWS * D_MODEL];
__device__ float g_k[MROWS * D_MODEL];
__device__ float g_v[MROWS * D_MODEL];
__device__ __nv_bfloat16 g_xh[MROWS * D_MODEL];
__device__ __nv_bfloat16 g_xl[MROWS * D_MODEL];
__device__ __nv_bfloat16 g_ah[MROWS * D_MODEL];
__device__ __nv_bfloat16 g_al[MROWS * D_MODEL];
__device__ __nv_bfloat16 g_wh[4][D_MODEL * D_MODEL];   // W^T [N][K] hi
__device__ __nv_bfloat16 g_wl[4][D_MODEL * D_MODEL];   // W^T [N][K] lo

// ---------------------------------------------------------------------------
// PTX helpers (compute_103-safe: mma.sync / ldmatrix / cp.async only)
// ---------------------------------------------------------------------------
__device__ __forceinline__ uint32_t smem_u32(const void* p) {
    uint32_t a;
    asm("{ .reg .u64 t; cvta.to.shared.u64 t, %1; cvt.u32.u64 %0, t; }" : "=r"(a) : "l"(p));
    return a;
}

__device__ __forceinline__ void cp16(uint32_t s, const void* g) {
    asm volatile("cp.async.cg.shared.global [%0], [%1], 16;" :: "r"(s), "l"(g));
}

__device__ __forceinline__ void ldsm4(uint32_t* r, uint32_t a) {
    asm volatile("ldmatrix.sync.aligned.m8n8.x4.shared.b16 {%0,%1,%2,%3}, [%4];"
                 : "=r"(r[0]), "=r"(r[1]), "=r"(r[2]), "=r"(r[3]) : "r"(a));
}

__device__ __forceinline__ void mma16816(float* d, const uint32_t* a, const uint32_t* b) {
    asm volatile(
        "mma.sync.aligned.m16n8k16.row.col.f32.bf16.bf16.f32 "
        "{%0,%1,%2,%3}, {%4,%5,%6,%7}, {%8,%9}, {%0,%1,%2,%3};"
        : "+f"(d[0]), "+f"(d[1]), "+f"(d[2]), "+f"(d[3])
        : "r"(a[0]), "r"(a[1]), "r"(a[2]), "r"(a[3]), "r"(b[0]), "r"(b[1]));
}

// ---------------------------------------------------------------------------
// fp32 -> (hi, lo) bf16 split, 4 elements/thread
// ---------------------------------------------------------------------------
__global__ __launch_bounds__(256)
void split_kernel(const float* __restrict__ in,
                  __nv_bfloat16* __restrict__ hi,
                  __nv_bfloat16* __restrict__ lo, int n4)
{
    int i = blockIdx.x * blockDim.x + threadIdx.x;
    if (i >= n4) return;
    float4 v = ((const float4*)in)[i];
    __nv_bfloat16 h0 = __float2bfloat16(v.x);
    __nv_bfloat16 h1 = __float2bfloat16(v.y);
    __nv_bfloat16 h2 = __float2bfloat16(v.z);
    __nv_bfloat16 h3 = __float2bfloat16(v.w);
    __nv_bfloat16 l0 = __float2bfloat16(v.x - __bfloat162float(h0));
    __nv_bfloat16 l1 = __float2bfloat16(v.y - __bfloat162float(h1));
    __nv_bfloat16 l2 = __float2bfloat16(v.z - __bfloat162float(h2));
    __nv_bfloat16 l3 = __float2bfloat16(v.w - __bfloat162float(h3));
    ((__nv_bfloat162*)hi)[2 * i]     = __nv_bfloat162(h0, h1);
    ((__nv_bfloat162*)hi)[2 * i + 1] = __nv_bfloat162(h2, h3);
    ((__nv_bfloat162*)lo)[2 * i]     = __nv_bfloat162(l0, l1);
    ((__nv_bfloat162*)lo)[2 * i + 1] = __nv_bfloat162(l2, l3);
}

// ---------------------------------------------------------------------------
// W [K,N] fp32 -> W^T [N,K] (hi, lo) bf16, 32x32 smem-tiled transpose
// ---------------------------------------------------------------------------
__global__ __launch_bounds__(256)
void wsplit_kernel(const float* __restrict__ W,
                   __nv_bfloat16* __restrict__ th,
                   __nv_bfloat16* __restrict__ tl)
{
    __shared__ float t[32][33];
    const int bx = blockIdx.x * 32;   // col block (N)
    const int by = blockIdx.y * 32;   // row block (K)
    const int x = threadIdx.x, y = threadIdx.y;   // 32 x 8
#pragma unroll
    for (int i = 0; i < 32; i += 8)
        t[y + i][x] = W[(size_t)(by + y + i) * D_MODEL + bx + x];
    __syncthreads();
#pragma unroll
    for (int i = 0; i < 32; i += 8) {
        float v = t[x][y + i];   // = W[by + x][bx + y + i]
        size_t o = (size_t)(bx + y + i) * D_MODEL + by + x;
        __nv_bfloat16 h = __float2bfloat16(v);
        th[o] = h;
        tl[o] = __float2bfloat16(v - __bfloat162float(h));
    }
}

// ---------------------------------------------------------------------------
// bf16 split-3-term GEMM via mma.sync (HMMA):
//   C[M,N] = A[M,K] @ Wt[N,K]^T + bias
// Tile 128x128xBK64, 256 threads (8 warps, 2x4), warp tile 64x32,
// cp.async 2-stage double buffer, padded smem (stride 72 bf16 = 144B).
// ---------------------------------------------------------------------------
#define BM 128
#define BN 128
#define BK 64
#define NCHUNK (D_MODEL / BK)        // 16
#define LDSTRIDE 72                   // bf16 elems per smem row (conflict-free)
#define MAT_BYTES (BM * LDSTRIDE * 2) // 18432
#define STAGE_BYTES (4 * MAT_BYTES)   // 73728 (Ah, Al, Bh, Bl)
#define GEMM_SMEM (2 * STAGE_BYTES)   // 147456

__global__ __launch_bounds__(256, 1)
void gemm_mma_kernel(const __nv_bfloat16* __restrict__ Ah,
                     const __nv_bfloat16* __restrict__ Al,
                     const __nv_bfloat16* __restrict__ Bh,
                     const __nv_bfloat16* __restrict__ Bl,
                     const float* __restrict__ bias,
                     float* __restrict__ C)
{
    extern __shared__ __align__(128) char smem[];
    const uint32_t sb = smem_u32(smem);
    const int tid  = threadIdx.x;
    const int wid  = tid >> 5;
    const int lane = tid & 31;
    const int wm = wid >> 2;          // 0..1  (M direction, 64 rows each)
    const int wn = wid & 3;           // 0..3  (N direction, 32 cols each)
    const int rowA0 = blockIdx.y * BM;
    const int rowB0 = blockIdx.x * BN;

    // ---- async loader: 1024 16B-chunks per matrix, 4 per thread ----
    auto issue = [&](int c, int s) {
        const uint32_t sbase = sb + (uint32_t)s * STAGE_BYTES;
#pragma unroll
        for (int i = 0; i < 4; ++i) {
            int cid = tid + i * 256;
            int row = cid >> 3;
            int kc  = cid & 7;
            uint32_t so = (uint32_t)(row * LDSTRIDE + kc * 8) * 2;
            size_t ga = (size_t)(rowA0 + row) * D_MODEL + c * BK + kc * 8;
            size_t gb = (size_t)(rowB0 + row) * D_MODEL + c * BK + kc * 8;
            cp16(sbase + 0 * MAT_BYTES + so, Ah + ga);
            cp16(sbase + 1 * MAT_BYTES + so, Al + ga);
            cp16(sbase + 2 * MAT_BYTES + so, Bh + gb);
            cp16(sbase + 3 * MAT_BYTES + so, Bl + gb);
        }
        asm volatile("cp.async.commit_group;" ::: "memory");
    };

    float acc[4][4][4];
#pragma unroll
    for (int mt = 0; mt < 4; ++mt)
#pragma unroll
        for (int nt = 0; nt < 4; ++nt)
#pragma unroll
            for (int i = 0; i < 4; ++i)
                acc[mt][nt][i] = 0.0f;

    // ldmatrix lane address components
    const int arow = lane & 15;               // A: rows 0-15
    const int acol = (lane >> 4) * 8;         // A: k 0 / 8
    const int brow = (lane & 7) + ((lane >> 4) << 3);   // B: n row within 16
    const int bcol = ((lane >> 3) & 1) * 8;   // B: k 0 / 8

    issue(0, 0);

    for (int c = 0; c < NCHUNK; ++c) {
        if (c + 1 < NCHUNK) {
            issue(c + 1, (c + 1) & 1);
            asm volatile("cp.async.wait_group 1;" ::: "memory");
        } else {
            asm volatile("cp.async.wait_group 0;" ::: "memory");
        }
        __syncthreads();

        const uint32_t sbase = sb + (uint32_t)(c & 1) * STAGE_BYTES;
        const uint32_t aH = sbase;
        const uint32_t aL = sbase + 1 * MAT_BYTES;
        const uint32_t bH = sbase + 2 * MAT_BYTES;
        const uint32_t bL = sbase + 3 * MAT_BYTES;

#pragma unroll
        for (int ks = 0; ks < 4; ++ks) {
            const int k0 = ks * 16;
            uint32_t ah[4][4], al[4][4];
#pragma unroll
            for (int mt = 0; mt < 4; ++mt) {
                uint32_t off = (uint32_t)((wm * 64 + mt * 16 + arow) * LDSTRIDE + k0 + acol) * 2;
                ldsm4(ah[mt], aH + off);
                ldsm4(al[mt], aL + off);
            }
            uint32_t bh[2][4], bl[2][4];
#pragma unroll
            for (int bt = 0; bt < 2; ++bt) {
                uint32_t off = (uint32_t)((wn * 32 + bt * 16 + brow) * LDSTRIDE + k0 + bcol) * 2;
                ldsm4(bh[bt], bH + off);
                ldsm4(bl[bt], bL + off);
            }
#pragma unroll
            for (int mt = 0; mt < 4; ++mt)
#pragma unroll
                for (int nt = 0; nt < 4; ++nt) {
                    const uint32_t* B_h = &bh[nt >> 1][(nt & 1) * 2];
                    const uint32_t* B_l = &bl[nt >> 1][(nt & 1) * 2];
                    mma16816(acc[mt][nt], ah[mt], B_h);   // hi*hi
                    mma16816(acc[mt][nt], ah[mt], B_l);   // hi*lo
                    mma16816(acc[mt][nt], al[mt], B_h);   // lo*hi
                }
        }
        __syncthreads();
    }

    // ---- epilogue: bias + fp32 store ----
    const int qr = lane >> 2;
    const int qc = (lane & 3) * 2;
#pragma unroll
    for (int mt = 0; mt < 4; ++mt) {
        const int r0 = rowA0 + wm * 64 + mt * 16 + qr;
#pragma unroll
        for (int nt = 0; nt < 4; ++nt) {
            const int col = rowB0 + wn * 32 + nt * 8 + qc;
            const float b0 = bias[col];
            const float b1 = bias[col + 1];
            float2 v0, v1;
            v0.x = acc[mt][nt][0] + b0;  v0.y = acc[mt][nt][1] + b1;
            v1.x = acc[mt][nt][2] + b0;  v1.y = acc[mt][nt][3] + b1;
            *(float2*)&C[(size_t)r0 * D_MODEL + col]       = v0;
            *(float2*)&C[(size_t)(r0 + 8) * D_MODEL + col] = v1;
        }
    }
}

// ---------------------------------------------------------------------------
// Dilated local attention, one warp per (b,h,q); writes bf16 hi/lo directly.
// ---------------------------------------------------------------------------
__global__ __launch_bounds__(256)
void dilated_attn_kernel(const float* __restrict__ Q,
                         const float* __restrict__ Kb,
                         const float* __restrict__ V,
                         __nv_bfloat16* __restrict__ Oh,
                         __nv_bfloat16* __restrict__ Ol,
                         const int* __restrict__ kptr,
                         const int* __restrict__ dptr)
{
    const int warp = (blockIdx.x * blockDim.x + threadIdx.x) >> 5;
    const int lane = threadIdx.x & 31;
    const int q  = warp % SEQ;
    const int bh = warp / SEQ;
    const int h  = bh % NHEADS;
    const int b  = bh / NHEADS;

    const int kw  = *kptr;
    const int dil = *dptr;

    const size_t rowq = (size_t)(b * SEQ + q) * D_MODEL + h * DHEAD;
    const float q0 = Q[rowq + lane];
    const float q1 = Q[rowq + lane + 32];
    const float scale = rsqrtf((float)DHEAD);

    float m = -1e30f, l = 0.0f, a0 = 0.0f, a1 = 0.0f;

    const int tmax = 2 * kw;
    for (int t = 0; t <= tmax; ++t) {
        const int j = q + (t - kw) * dil;
        if (j < 0 || j >= SEQ) continue;
        const size_t rowj = (size_t)(b * SEQ + j) * D_MODEL + h * DHEAD;

        float p = q0 * Kb[rowj + lane] + q1 * Kb[rowj + lane + 32];
#pragma unroll
        for (int s = 16; s > 0; s >>= 1)
            p += __shfl_xor_sync(0xffffffffu, p, s);
        const float sc = p * scale;

        const float mn   = fmaxf(m, sc);
        const float corr = __expf(m - mn);
        const float e    = __expf(sc - mn);
        a0 = a0 * corr + e * V[rowj + lane];
        a1 = a1 * corr + e * V[rowj + lane + 32];
        l  = l * corr + e;
        m  = mn;
    }

    const float inv = 1.0f / l;
    const float o0 = a0 * inv, o1 = a1 * inv;
    __nv_bfloat16 h0 = __float2bfloat16(o0);
    __nv_bfloat16 h1 = __float2bfloat16(o1);
    Oh[rowq + lane]      = h0;
    Oh[rowq + lane + 32] = h1;
    Ol[rowq + lane]      = __float2bfloat16(o0 - __bfloat162float(h0));
    Ol[rowq + lane + 32] = __float2bfloat16(o1 - __bfloat162float(h1));
}

// ---------------------------------------------------------------------------
// Launch
// ---------------------------------------------------------------------------
extern "C" void kernel_launch(void* const* d_in, const int* in_sizes, int n_in,
                              void* d_out, int out_size)
{
    const float* x  = (const float*)d_in[0];
    const float* Wq = (const float*)d_in[1];
    const float* bq = (const float*)d_in[2];
    const float* Wk = (const float*)d_in[3];
    const float* bk = (const float*)d_in[4];
    const float* Wv = (const float*)d_in[5];
    const float* bv = (const float*)d_in[6];
    const float* Wo = (const float*)d_in[7];
    const float* bo = (const float*)d_in[8];
    const int*   kp = (const int*)d_in[9];
    const int*   dp = (const int*)d_in[10];
    float* out = (float*)d_out;

    void *pq, *pk, *pv, *pxh, *pxl, *pah, *pal, *pwh, *pwl;
    cudaGetSymbolAddress(&pq,  g_q);
    cudaGetSymbolAddress(&pk,  g_k);
    cudaGetSymbolAddress(&pv,  g_v);
    cudaGetSymbolAddress(&pxh, g_xh);
    cudaGetSymbolAddress(&pxl, g_xl);
    cudaGetSymbolAddress(&pah, g_ah);
    cudaGetSymbolAddress(&pal, g_al);
    cudaGetSymbolAddress(&pwh, g_wh);
    cudaGetSymbolAddress(&pwl, g_wl);
    float* qbuf = (float*)pq;
    float* kbuf = (float*)pk;
    float* vbuf = (float*)pv;
    __nv_bfloat16* xh = (__nv_bfloat16*)pxh;
    __nv_bfloat16* xl = (__nv_bfloat16*)pxl;
    __nv_bfloat16* ah = (__nv_bfloat16*)pah;
    __nv_bfloat16* al = (__nv_bfloat16*)pal;
    __nv_bfloat16* wh = (__nv_bfloat16*)pwh;
    __nv_bfloat16* wl = (__nv_bfloat16*)pwl;
    const size_t WSZ = (size_t)D_MODEL * D_MODEL;

    cudaFuncSetAttribute(gemm_mma_kernel, cudaFuncAttributeMaxDynamicSharedMemorySize, GEMM_SMEM);

    // 1) split x into bf16 hi/lo
    {
        int n4 = MROWS * D_MODEL / 4;
        split_kernel<<<(n4 + 255) / 256, 256>>>(x, xh, xl, n4);
    }
    // 2) transpose + split weights
    {
        dim3 tb(32, 8), tg(D_MODEL / 32, D_MODEL / 32);
        wsplit_kernel<<<tg, tb>>>(Wq, wh + 0 * WSZ, wl + 0 * WSZ);
        wsplit_kernel<<<tg, tb>>>(Wk, wh + 1 * WSZ, wl + 1 * WSZ);
        wsplit_kernel<<<tg, tb>>>(Wv, wh + 2 * WSZ, wl + 2 * WSZ);
        wsplit_kernel<<<tg, tb>>>(Wo, wh + 3 * WSZ, wl + 3 * WSZ);
    }
    // 3) QKV projections on tensor cores (HMMA)
    {
        dim3 gg(D_MODEL / BN, MROWS / BM);   // (8, 64)
        gemm_mma_kernel<<<gg, 256, GEMM_SMEM>>>(xh, xl, wh + 0 * WSZ, wl + 0 * WSZ, bq, qbuf);
        gemm_mma_kernel<<<gg, 256, GEMM_SMEM>>>(xh, xl, wh + 1 * WSZ, wl + 1 * WSZ, bk, kbuf);
        gemm_mma_kernel<<<gg, 256, GEMM_SMEM>>>(xh, xl, wh + 2 * WSZ, wl + 2 * WSZ, bv, vbuf);
    }
    // 4) dilated attention -> bf16 hi/lo
    {
        const int n_warps  = BATCH * NHEADS * SEQ;
        const int n_blocks = n_warps / 8;
        dilated_attn_kernel<<<n_blocks, 256>>>(qbuf, kbuf, vbuf, ah, al, kp, dp);
    }
    // 5) output projection -> d_out
    {
        dim3 gg(D_MODEL / BN, MROWS / BM);
        gemm_mma_kernel<<<gg, 256, GEMM_SMEM>>>(ah, al, wh + 3 * WSZ, wl + 3 * WSZ, bo, out);
    }
}

// round 7
// speedup vs baseline: 2.5768x; 1.0641x over previous
#include <cuda_runtime.h>
#include <cuda_bf16.h>
#include <cstdint>
#include <math.h>

// Problem constants
#define D_MODEL 1024
#define NHEADS  16
#define DHEAD   64
#define BATCH   4
#define SEQ     2048
#define MROWS   (BATCH * SEQ)   // 8192

// ---------------------------------------------------------------------------
// Scratch (__device__ globals; no cudaMalloc allowed)
// ---------------------------------------------------------------------------
__device__ float g_q[MROWS * D_MODEL];
__device__ float g_k[MROWS * D_MODEL];
__device__ float g_v[MROWS * D_MODEL];
__device__ __nv_bfloat16 g_xh[MROWS * D_MODEL];
__device__ __nv_bfloat16 g_xl[MROWS * D_MODEL];
__device__ __nv_bfloat16 g_ah[MROWS * D_MODEL];
__device__ __nv_bfloat16 g_al[MROWS * D_MODEL];
__device__ __nv_bfloat16 g_wh[4][D_MODEL * D_MODEL];   // W^T [N][K] hi
__device__ __nv_bfloat16 g_wl[4][D_MODEL * D_MODEL];   // W^T [N][K] lo

// ---------------------------------------------------------------------------
// PTX helpers (compute_103-safe: mma.sync / ldmatrix / cp.async only)
// ---------------------------------------------------------------------------
__device__ __forceinline__ uint32_t smem_u32(const void* p) {
    uint32_t a;
    asm("{ .reg .u64 t; cvta.to.shared.u64 t, %1; cvt.u32.u64 %0, t; }" : "=r"(a) : "l"(p));
    return a;
}

__device__ __forceinline__ void cp16(uint32_t s, const void* g) {
    asm volatile("cp.async.cg.shared.global [%0], [%1], 16;" :: "r"(s), "l"(g));
}

__device__ __forceinline__ void ldsm4(uint32_t* r, uint32_t a) {
    asm volatile("ldmatrix.sync.aligned.m8n8.x4.shared.b16 {%0,%1,%2,%3}, [%4];"
                 : "=r"(r[0]), "=r"(r[1]), "=r"(r[2]), "=r"(r[3]) : "r"(a));
}

__device__ __forceinline__ void mma16816(float* d, const uint32_t* a, const uint32_t* b) {
    asm volatile(
        "mma.sync.aligned.m16n8k16.row.col.f32.bf16.bf16.f32 "
        "{%0,%1,%2,%3}, {%4,%5,%6,%7}, {%8,%9}, {%0,%1,%2,%3};"
        : "+f"(d[0]), "+f"(d[1]), "+f"(d[2]), "+f"(d[3])
        : "r"(a[0]), "r"(a[1]), "r"(a[2]), "r"(a[3]), "r"(b[0]), "r"(b[1]));
}

// ---------------------------------------------------------------------------
// fp32 -> (hi, lo) bf16 split, 4 elements/thread
// ---------------------------------------------------------------------------
__global__ __launch_bounds__(256)
void split_kernel(const float* __restrict__ in,
                  __nv_bfloat16* __restrict__ hi,
                  __nv_bfloat16* __restrict__ lo, int n4)
{
    int i = blockIdx.x * blockDim.x + threadIdx.x;
    if (i >= n4) return;
    float4 v = ((const float4*)in)[i];
    __nv_bfloat16 h0 = __float2bfloat16(v.x);
    __nv_bfloat16 h1 = __float2bfloat16(v.y);
    __nv_bfloat16 h2 = __float2bfloat16(v.z);
    __nv_bfloat16 h3 = __float2bfloat16(v.w);
    __nv_bfloat16 l0 = __float2bfloat16(v.x - __bfloat162float(h0));
    __nv_bfloat16 l1 = __float2bfloat16(v.y - __bfloat162float(h1));
    __nv_bfloat16 l2 = __float2bfloat16(v.z - __bfloat162float(h2));
    __nv_bfloat16 l3 = __float2bfloat16(v.w - __bfloat162float(h3));
    ((__nv_bfloat162*)hi)[2 * i]     = __nv_bfloat162(h0, h1);
    ((__nv_bfloat162*)hi)[2 * i + 1] = __nv_bfloat162(h2, h3);
    ((__nv_bfloat162*)lo)[2 * i]     = __nv_bfloat162(l0, l1);
    ((__nv_bfloat162*)lo)[2 * i + 1] = __nv_bfloat162(l2, l3);
}

// ---------------------------------------------------------------------------
// W [K,N] fp32 -> W^T [N,K] (hi, lo) bf16; blockIdx.z selects which weight
// ---------------------------------------------------------------------------
__global__ __launch_bounds__(256)
void wsplit_kernel(const float* __restrict__ W0, const float* __restrict__ W1,
                   const float* __restrict__ W2, const float* __restrict__ W3,
                   __nv_bfloat16* __restrict__ th_base,
                   __nv_bfloat16* __restrict__ tl_base)
{
    __shared__ float t[32][33];
    const int wsel = blockIdx.z;
    const float* W = (wsel == 0) ? W0 : (wsel == 1) ? W1 : (wsel == 2) ? W2 : W3;
    __nv_bfloat16* th = th_base + (size_t)wsel * D_MODEL * D_MODEL;
    __nv_bfloat16* tl = tl_base + (size_t)wsel * D_MODEL * D_MODEL;
    const int bx = blockIdx.x * 32;   // col block (N)
    const int by = blockIdx.y * 32;   // row block (K)
    const int x = threadIdx.x, y = threadIdx.y;   // 32 x 8
#pragma unroll
    for (int i = 0; i < 32; i += 8)
        t[y + i][x] = W[(size_t)(by + y + i) * D_MODEL + bx + x];
    __syncthreads();
#pragma unroll
    for (int i = 0; i < 32; i += 8) {
        float v = t[x][y + i];   // = W[by + x][bx + y + i]
        size_t o = (size_t)(bx + y + i) * D_MODEL + by + x;
        __nv_bfloat16 h = __float2bfloat16(v);
        th[o] = h;
        tl[o] = __float2bfloat16(v - __bfloat162float(h));
    }
}

// ---------------------------------------------------------------------------
// bf16 split-3-term GEMM core via mma.sync (HMMA):
//   C[M,N] = A[M,K] @ Wt[N,K]^T + bias
// Tile 128x128xBK64, 256 threads (8 warps, 2x4), warp tile 64x32,
// cp.async 2-stage double buffer, padded smem (stride 72 bf16 = 144B).
// ---------------------------------------------------------------------------
#define BM 128
#define BN 128
#define BK 64
#define NCHUNK (D_MODEL / BK)        // 16
#define LDSTRIDE 72                   // bf16 elems per smem row (conflict-free)
#define MAT_BYTES (BM * LDSTRIDE * 2) // 18432
#define STAGE_BYTES (4 * MAT_BYTES)   // 73728 (Ah, Al, Bh, Bl)
#define GEMM_SMEM (2 * STAGE_BYTES)   // 147456

__device__ __forceinline__
void gemm_body(const __nv_bfloat16* __restrict__ Ah,
               const __nv_bfloat16* __restrict__ Al,
               const __nv_bfloat16* __restrict__ Bh,
               const __nv_bfloat16* __restrict__ Bl,
               const float* __restrict__ bias,
               float* __restrict__ C,
               int rowA0, int rowB0, char* smem)
{
    const uint32_t sb = smem_u32(smem);
    const int tid  = threadIdx.x;
    const int wid  = tid >> 5;
    const int lane = tid & 31;
    const int wm = wid >> 2;          // 0..1  (M direction, 64 rows each)
    const int wn = wid & 3;           // 0..3  (N direction, 32 cols each)

    // ---- async loader: 1024 16B-chunks per matrix, 4 per thread ----
    auto issue = [&](int c, int s) {
        const uint32_t sbase = sb + (uint32_t)s * STAGE_BYTES;
#pragma unroll
        for (int i = 0; i < 4; ++i) {
            int cid = tid + i * 256;
            int row = cid >> 3;
            int kc  = cid & 7;
            uint32_t so = (uint32_t)(row * LDSTRIDE + kc * 8) * 2;
            size_t ga = (size_t)(rowA0 + row) * D_MODEL + c * BK + kc * 8;
            size_t gb = (size_t)(rowB0 + row) * D_MODEL + c * BK + kc * 8;
            cp16(sbase + 0 * MAT_BYTES + so, Ah + ga);
            cp16(sbase + 1 * MAT_BYTES + so, Al + ga);
            cp16(sbase + 2 * MAT_BYTES + so, Bh + gb);
            cp16(sbase + 3 * MAT_BYTES + so, Bl + gb);
        }
        asm volatile("cp.async.commit_group;" ::: "memory");
    };

    float acc[4][4][4];
#pragma unroll
    for (int mt = 0; mt < 4; ++mt)
#pragma unroll
        for (int nt = 0; nt < 4; ++nt)
#pragma unroll
            for (int i = 0; i < 4; ++i)
                acc[mt][nt][i] = 0.0f;

    const int arow = lane & 15;
    const int acol = (lane >> 4) * 8;
    const int brow = (lane & 7) + ((lane >> 4) << 3);
    const int bcol = ((lane >> 3) & 1) * 8;

    issue(0, 0);

    for (int c = 0; c < NCHUNK; ++c) {
        if (c + 1 < NCHUNK) {
            issue(c + 1, (c + 1) & 1);
            asm volatile("cp.async.wait_group 1;" ::: "memory");
        } else {
            asm volatile("cp.async.wait_group 0;" ::: "memory");
        }
        __syncthreads();

        const uint32_t sbase = sb + (uint32_t)(c & 1) * STAGE_BYTES;
        const uint32_t aH = sbase;
        const uint32_t aL = sbase + 1 * MAT_BYTES;
        const uint32_t bH = sbase + 2 * MAT_BYTES;
        const uint32_t bL = sbase + 3 * MAT_BYTES;

#pragma unroll
        for (int ks = 0; ks < 4; ++ks) {
            const int k0 = ks * 16;
            uint32_t ah[4][4], al[4][4];
#pragma unroll
            for (int mt = 0; mt < 4; ++mt) {
                uint32_t off = (uint32_t)((wm * 64 + mt * 16 + arow) * LDSTRIDE + k0 + acol) * 2;
                ldsm4(ah[mt], aH + off);
                ldsm4(al[mt], aL + off);
            }
            uint32_t bh[2][4], bl[2][4];
#pragma unroll
            for (int bt = 0; bt < 2; ++bt) {
                uint32_t off = (uint32_t)((wn * 32 + bt * 16 + brow) * LDSTRIDE + k0 + bcol) * 2;
                ldsm4(bh[bt], bH + off);
                ldsm4(bl[bt], bL + off);
            }
#pragma unroll
            for (int mt = 0; mt < 4; ++mt)
#pragma unroll
                for (int nt = 0; nt < 4; ++nt) {
                    const uint32_t* B_h = &bh[nt >> 1][(nt & 1) * 2];
                    const uint32_t* B_l = &bl[nt >> 1][(nt & 1) * 2];
                    mma16816(acc[mt][nt], ah[mt], B_h);   // hi*hi
                    mma16816(acc[mt][nt], ah[mt], B_l);   // hi*lo
                    mma16816(acc[mt][nt], al[mt], B_h);   // lo*hi
                }
        }
        __syncthreads();
    }

    // ---- epilogue ----
    const int qr = lane >> 2;
    const int qc = (lane & 3) * 2;
#pragma unroll
    for (int mt = 0; mt < 4; ++mt) {
        const int r0 = rowA0 + wm * 64 + mt * 16 + qr;
#pragma unroll
        for (int nt = 0; nt < 4; ++nt) {
            const int col = rowB0 + wn * 32 + nt * 8 + qc;
            const float b0 = bias[col];
            const float b1 = bias[col + 1];
            float2 v0, v1;
            v0.x = acc[mt][nt][0] + b0;  v0.y = acc[mt][nt][1] + b1;
            v1.x = acc[mt][nt][2] + b0;  v1.y = acc[mt][nt][3] + b1;
            *(float2*)&C[(size_t)r0 * D_MODEL + col]       = v0;
            *(float2*)&C[(size_t)(r0 + 8) * D_MODEL + col] = v1;
        }
    }
}

// Fused QKV: grid.x = 24 (3 outputs x 8 N-tiles), grid.y = 64 (M-tiles)
__global__ __launch_bounds__(256, 1)
void gemm_qkv_kernel(const __nv_bfloat16* __restrict__ xh,
                     const __nv_bfloat16* __restrict__ xl,
                     const __nv_bfloat16* __restrict__ wh,
                     const __nv_bfloat16* __restrict__ wl,
                     const float* __restrict__ bq, const float* __restrict__ bk,
                     const float* __restrict__ bv,
                     float* __restrict__ qb, float* __restrict__ kb,
                     float* __restrict__ vb)
{
    extern __shared__ __align__(128) char smem[];
    const int which = blockIdx.x >> 3;
    const int bxn   = blockIdx.x & 7;
    const size_t WSZ = (size_t)D_MODEL * D_MODEL;
    const float* bias = (which == 0) ? bq : (which == 1) ? bk : bv;
    float* C = (which == 0) ? qb : (which == 1) ? kb : vb;
    gemm_body(xh, xl, wh + which * WSZ, wl + which * WSZ, bias, C,
              blockIdx.y * BM, bxn * BN, smem);
}

// Single GEMM (output projection)
__global__ __launch_bounds__(256, 1)
void gemm_o_kernel(const __nv_bfloat16* __restrict__ Ah,
                   const __nv_bfloat16* __restrict__ Al,
                   const __nv_bfloat16* __restrict__ Bh,
                   const __nv_bfloat16* __restrict__ Bl,
                   const float* __restrict__ bias,
                   float* __restrict__ C)
{
    extern __shared__ __align__(128) char smem[];
    gemm_body(Ah, Al, Bh, Bl, bias, C, blockIdx.y * BM, blockIdx.x * BN, smem);
}

// ---------------------------------------------------------------------------
// Tiled dilated attention.
// One block per (b, h, 32-query tile). K/V window staged in smem (<= 96 rows).
// 8 warps x 4 queries each; per-query online softmax, 2 head dims per lane.
// ---------------------------------------------------------------------------
#define QTILE 32
#define CAP_ROWS 96
#define ATT_SMEM (2 * CAP_ROWS * DHEAD * 4)   // 49152 B

__global__ __launch_bounds__(256)
void attn_tile_kernel(const float* __restrict__ Q,
                      const float* __restrict__ Kb,
                      const float* __restrict__ V,
                      __nv_bfloat16* __restrict__ Oh,
                      __nv_bfloat16* __restrict__ Ol,
                      const int* __restrict__ kptr,
                      const int* __restrict__ dptr)
{
    extern __shared__ __align__(16) float sm[];
    float* Ks = sm;
    float* Vs = sm + CAP_ROWS * DHEAD;

    const int tid  = threadIdx.x;
    const int wid  = tid >> 5;
    const int lane = tid & 31;

    // block -> (b, h, q-tile)
    const int qt = blockIdx.x & (SEQ / QTILE - 1);
    const int bh = blockIdx.x / (SEQ / QTILE);
    const int h  = bh % NHEADS;
    const int b  = bh / NHEADS;
    const int q0 = qt * QTILE;

    const int kw   = *kptr;
    const int dil  = *dptr;
    const int koff = kw * dil;

    const int base = max(0, q0 - koff);
    const int top  = min(SEQ - 1, q0 + QTILE - 1 + koff);
    const int rows = top - base + 1;
    const bool cached = (rows <= CAP_ROWS);

    const size_t gbase = (size_t)(b * SEQ) * D_MODEL + h * DHEAD;

    if (cached) {
        // load rows*16 float4 chunks per matrix; thread t -> chunk t, t+256, ...
        const int nchunk = rows * (DHEAD / 4);   // <= 1536
        for (int c = tid; c < nchunk; c += 256) {
            const int r = c >> 4;
            const int d4 = (c & 15) * 4;
            const size_t g = gbase + (size_t)(base + r) * D_MODEL + d4;
            *(float4*)&Ks[r * DHEAD + d4] = *(const float4*)&Kb[g];
            *(float4*)&Vs[r * DHEAD + d4] = *(const float4*)&V[g];
        }
        __syncthreads();
    }

    const float scale = rsqrtf((float)DHEAD);
    const int tmax = 2 * kw;

#pragma unroll
    for (int qi = 0; qi < 4; ++qi) {
        const int q = q0 + wid * 4 + qi;
        const size_t rowq = gbase + (size_t)q * D_MODEL;
        const float q0f = Q[rowq + lane];
        const float q1f = Q[rowq + lane + 32];

        float m = -1e30f, l = 0.0f, a0 = 0.0f, a1 = 0.0f;

        for (int t = 0; t <= tmax; ++t) {
            const int j = q + (t - kw) * dil;
            if (j < 0 || j >= SEQ) continue;

            float k0, k1, v0, v1;
            if (cached) {
                const int rj = (j - base) * DHEAD;
                k0 = Ks[rj + lane];      k1 = Ks[rj + lane + 32];
                v0 = Vs[rj + lane];      v1 = Vs[rj + lane + 32];
            } else {
                const size_t rowj = gbase + (size_t)j * D_MODEL;
                k0 = Kb[rowj + lane];    k1 = Kb[rowj + lane + 32];
                v0 = V[rowj + lane];     v1 = V[rowj + lane + 32];
            }

            float p = q0f * k0 + q1f * k1;
#pragma unroll
            for (int s = 16; s > 0; s >>= 1)
                p += __shfl_xor_sync(0xffffffffu, p, s);
            const float sc = p * scale;

            const float mn   = fmaxf(m, sc);
            const float corr = __expf(m - mn);
            const float e    = __expf(sc - mn);
            a0 = a0 * corr + e * v0;
            a1 = a1 * corr + e * v1;
            l  = l * corr + e;
            m  = mn;
        }

        const float inv = 1.0f / l;
        const float o0 = a0 * inv, o1 = a1 * inv;
        __nv_bfloat16 h0 = __float2bfloat16(o0);
        __nv_bfloat16 h1 = __float2bfloat16(o1);
        Oh[rowq + lane]      = h0;
        Oh[rowq + lane + 32] = h1;
        Ol[rowq + lane]      = __float2bfloat16(o0 - __bfloat162float(h0));
        Ol[rowq + lane + 32] = __float2bfloat16(o1 - __bfloat162float(h1));
    }
}

// ---------------------------------------------------------------------------
// Launch
// ---------------------------------------------------------------------------
extern "C" void kernel_launch(void* const* d_in, const int* in_sizes, int n_in,
                              void* d_out, int out_size)
{
    const float* x  = (const float*)d_in[0];
    const float* Wq = (const float*)d_in[1];
    const float* bq = (const float*)d_in[2];
    const float* Wk = (const float*)d_in[3];
    const float* bk = (const float*)d_in[4];
    const float* Wv = (const float*)d_in[5];
    const float* bv = (const float*)d_in[6];
    const float* Wo = (const float*)d_in[7];
    const float* bo = (const float*)d_in[8];
    const int*   kp = (const int*)d_in[9];
    const int*   dp = (const int*)d_in[10];
    float* out = (float*)d_out;

    void *pq, *pk, *pv, *pxh, *pxl, *pah, *pal, *pwh, *pwl;
    cudaGetSymbolAddress(&pq,  g_q);
    cudaGetSymbolAddress(&pk,  g_k);
    cudaGetSymbolAddress(&pv,  g_v);
    cudaGetSymbolAddress(&pxh, g_xh);
    cudaGetSymbolAddress(&pxl, g_xl);
    cudaGetSymbolAddress(&pah, g_ah);
    cudaGetSymbolAddress(&pal, g_al);
    cudaGetSymbolAddress(&pwh, g_wh);
    cudaGetSymbolAddress(&pwl, g_wl);
    float* qbuf = (float*)pq;
    float* kbuf = (float*)pk;
    float* vbuf = (float*)pv;
    __nv_bfloat16* xh = (__nv_bfloat16*)pxh;
    __nv_bfloat16* xl = (__nv_bfloat16*)pxl;
    __nv_bfloat16* ah = (__nv_bfloat16*)pah;
    __nv_bfloat16* al = (__nv_bfloat16*)pal;
    __nv_bfloat16* wh = (__nv_bfloat16*)pwh;
    __nv_bfloat16* wl = (__nv_bfloat16*)pwl;
    const size_t WSZ = (size_t)D_MODEL * D_MODEL;

    cudaFuncSetAttribute(gemm_qkv_kernel, cudaFuncAttributeMaxDynamicSharedMemorySize, GEMM_SMEM);
    cudaFuncSetAttribute(gemm_o_kernel,   cudaFuncAttributeMaxDynamicSharedMemorySize, GEMM_SMEM);
    cudaFuncSetAttribute(attn_tile_kernel, cudaFuncAttributeMaxDynamicSharedMemorySize, ATT_SMEM);

    // 1) split x into bf16 hi/lo
    {
        int n4 = MROWS * D_MODEL / 4;
        split_kernel<<<(n4 + 255) / 256, 256>>>(x, xh, xl, n4);
    }
    // 2) transpose + split all 4 weights (one launch)
    {
        dim3 tb(32, 8), tg(D_MODEL / 32, D_MODEL / 32, 4);
        wsplit_kernel<<<tg, tb>>>(Wq, Wk, Wv, Wo, wh, wl);
    }
    // 3) fused QKV projections (HMMA)
    {
        dim3 gg(3 * (D_MODEL / BN), MROWS / BM);   // (24, 64)
        gemm_qkv_kernel<<<gg, 256, GEMM_SMEM>>>(xh, xl, wh, wl, bq, bk, bv,
                                                qbuf, kbuf, vbuf);
    }
    // 4) tiled dilated attention -> bf16 hi/lo
    {
        const int n_blocks = BATCH * NHEADS * (SEQ / QTILE);   // 4096
        attn_tile_kernel<<<n_blocks, 256, ATT_SMEM>>>(qbuf, kbuf, vbuf, ah, al, kp, dp);
    }
    // 5) output projection -> d_out
    {
        dim3 gg(D_MODEL / BN, MROWS / BM);
        gemm_o_kernel<<<gg, 256, GEMM_SMEM>>>(ah, al, wh + 3 * WSZ, wl + 3 * WSZ, bo, out);
    }
}

// round 8
// speedup vs baseline: 2.7816x; 1.0795x over previous
#include <cuda_runtime.h>
#include <cuda_bf16.h>
#include <cstdint>
#include <math.h>

// Problem constants
#define D_MODEL 1024
#define NHEADS  16
#define DHEAD   64
#define BATCH   4
#define SEQ     2048
#define MROWS   (BATCH * SEQ)   // 8192

// ---------------------------------------------------------------------------
// Scratch (__device__ globals; no cudaMalloc allowed)
// ---------------------------------------------------------------------------
__device__ float g_q[MROWS * D_MODEL];
__device__ float g_k[MROWS * D_MODEL];
__device__ float g_v[MROWS * D_MODEL];
__device__ float g_xt[MROWS * D_MODEL];                 // x tf32-rounded
__device__ float g_wt[2][D_MODEL * D_MODEL];            // Wq^T, Wk^T tf32-rounded
__device__ __nv_bfloat16 g_xh[MROWS * D_MODEL];
__device__ __nv_bfloat16 g_xl[MROWS * D_MODEL];
__device__ __nv_bfloat16 g_ah[MROWS * D_MODEL];
__device__ __nv_bfloat16 g_al[MROWS * D_MODEL];
__device__ __nv_bfloat16 g_wh[4][D_MODEL * D_MODEL];   // W^T hi (slots 2,3 used)
__device__ __nv_bfloat16 g_wl[4][D_MODEL * D_MODEL];   // W^T lo (slots 2,3 used)

// ---------------------------------------------------------------------------
// PTX helpers (compute_103-safe)
// ---------------------------------------------------------------------------
__device__ __forceinline__ uint32_t smem_u32(const void* p) {
    uint32_t a;
    asm("{ .reg .u64 t; cvta.to.shared.u64 t, %1; cvt.u32.u64 %0, t; }" : "=r"(a) : "l"(p));
    return a;
}
__device__ __forceinline__ void cp16(uint32_t s, const void* g) {
    asm volatile("cp.async.cg.shared.global [%0], [%1], 16;" :: "r"(s), "l"(g));
}
__device__ __forceinline__ void ldsm4(uint32_t* r, uint32_t a) {
    asm volatile("ldmatrix.sync.aligned.m8n8.x4.shared.b16 {%0,%1,%2,%3}, [%4];"
                 : "=r"(r[0]), "=r"(r[1]), "=r"(r[2]), "=r"(r[3]) : "r"(a));
}
__device__ __forceinline__ void mma16816(float* d, const uint32_t* a, const uint32_t* b) {
    asm volatile(
        "mma.sync.aligned.m16n8k16.row.col.f32.bf16.bf16.f32 "
        "{%0,%1,%2,%3}, {%4,%5,%6,%7}, {%8,%9}, {%0,%1,%2,%3};"
        : "+f"(d[0]), "+f"(d[1]), "+f"(d[2]), "+f"(d[3])
        : "r"(a[0]), "r"(a[1]), "r"(a[2]), "r"(a[3]), "r"(b[0]), "r"(b[1]));
}
__device__ __forceinline__ void mma1688_tf32(float* d, const uint32_t* a, uint32_t b0, uint32_t b1) {
    asm volatile(
        "mma.sync.aligned.m16n8k8.row.col.f32.tf32.tf32.f32 "
        "{%0,%1,%2,%3}, {%4,%5,%6,%7}, {%8,%9}, {%0,%1,%2,%3};"
        : "+f"(d[0]), "+f"(d[1]), "+f"(d[2]), "+f"(d[3])
        : "r"(a[0]), "r"(a[1]), "r"(a[2]), "r"(a[3]), "r"(b0), "r"(b1));
}
__device__ __forceinline__ uint32_t f2tf32(float v) {
    uint32_t u;
    asm("cvt.rna.tf32.f32 %0, %1;" : "=r"(u) : "f"(v));
    return u;
}

// ---------------------------------------------------------------------------
// fp32 -> (hi, lo) bf16 split + tf32-rounded copy
// ---------------------------------------------------------------------------
__global__ __launch_bounds__(256)
void split_kernel(const float* __restrict__ in,
                  __nv_bfloat16* __restrict__ hi,
                  __nv_bfloat16* __restrict__ lo,
                  float* __restrict__ tf, int n4)
{
    int i = blockIdx.x * blockDim.x + threadIdx.x;
    if (i >= n4) return;
    float4 v = ((const float4*)in)[i];
    __nv_bfloat16 h0 = __float2bfloat16(v.x);
    __nv_bfloat16 h1 = __float2bfloat16(v.y);
    __nv_bfloat16 h2 = __float2bfloat16(v.z);
    __nv_bfloat16 h3 = __float2bfloat16(v.w);
    __nv_bfloat16 l0 = __float2bfloat16(v.x - __bfloat162float(h0));
    __nv_bfloat16 l1 = __float2bfloat16(v.y - __bfloat162float(h1));
    __nv_bfloat16 l2 = __float2bfloat16(v.z - __bfloat162float(h2));
    __nv_bfloat16 l3 = __float2bfloat16(v.w - __bfloat162float(h3));
    ((__nv_bfloat162*)hi)[2 * i]     = __nv_bfloat162(h0, h1);
    ((__nv_bfloat162*)hi)[2 * i + 1] = __nv_bfloat162(h2, h3);
    ((__nv_bfloat162*)lo)[2 * i]     = __nv_bfloat162(l0, l1);
    ((__nv_bfloat162*)lo)[2 * i + 1] = __nv_bfloat162(l2, l3);
    uint4 t;
    t.x = f2tf32(v.x); t.y = f2tf32(v.y); t.z = f2tf32(v.z); t.w = f2tf32(v.w);
    ((uint4*)tf)[i] = t;
}

// ---------------------------------------------------------------------------
// W [K,N] fp32 -> W^T [N,K]; wsel 0,1 -> tf32 fp32; wsel 2,3 -> bf16 hi/lo
// ---------------------------------------------------------------------------
__global__ __launch_bounds__(256)
void wsplit_kernel(const float* __restrict__ W0, const float* __restrict__ W1,
                   const float* __restrict__ W2, const float* __restrict__ W3,
                   float* __restrict__ wt_base,
                   __nv_bfloat16* __restrict__ th_base,
                   __nv_bfloat16* __restrict__ tl_base)
{
    __shared__ float t[32][33];
    const int wsel = blockIdx.z;
    const float* W = (wsel == 0) ? W0 : (wsel == 1) ? W1 : (wsel == 2) ? W2 : W3;
    const int bx = blockIdx.x * 32;   // col block (N)
    const int by = blockIdx.y * 32;   // row block (K)
    const int x = threadIdx.x, y = threadIdx.y;   // 32 x 8
#pragma unroll
    for (int i = 0; i < 32; i += 8)
        t[y + i][x] = W[(size_t)(by + y + i) * D_MODEL + bx + x];
    __syncthreads();
    if (wsel < 2) {
        float* wt = wt_base + (size_t)wsel * D_MODEL * D_MODEL;
#pragma unroll
        for (int i = 0; i < 32; i += 8) {
            float v = t[x][y + i];
            size_t o = (size_t)(bx + y + i) * D_MODEL + by + x;
            wt[o] = __uint_as_float(f2tf32(v));
        }
    } else {
        __nv_bfloat16* th = th_base + (size_t)wsel * D_MODEL * D_MODEL;
        __nv_bfloat16* tl = tl_base + (size_t)wsel * D_MODEL * D_MODEL;
#pragma unroll
        for (int i = 0; i < 32; i += 8) {
            float v = t[x][y + i];
            size_t o = (size_t)(bx + y + i) * D_MODEL + by + x;
            __nv_bfloat16 h = __float2bfloat16(v);
            th[o] = h;
            tl[o] = __float2bfloat16(v - __bfloat162float(h));
        }
    }
}

// ---------------------------------------------------------------------------
// bf16 split-3-term GEMM core via mma.sync (unchanged; used for V and O)
// ---------------------------------------------------------------------------
#define BM 128
#define BN 128
#define BK 64
#define NCHUNK (D_MODEL / BK)        // 16
#define LDSTRIDE 72
#define MAT_BYTES (BM * LDSTRIDE * 2)
#define STAGE_BYTES (4 * MAT_BYTES)
#define GEMM_SMEM (2 * STAGE_BYTES)   // 147456

__device__ __forceinline__
void gemm_body(const __nv_bfloat16* __restrict__ Ah,
               const __nv_bfloat16* __restrict__ Al,
               const __nv_bfloat16* __restrict__ Bh,
               const __nv_bfloat16* __restrict__ Bl,
               const float* __restrict__ bias,
               float* __restrict__ C,
               int rowA0, int rowB0, char* smem)
{
    const uint32_t sb = smem_u32(smem);
    const int tid  = threadIdx.x;
    const int wid  = tid >> 5;
    const int lane = tid & 31;
    const int wm = wid >> 2;
    const int wn = wid & 3;

    auto issue = [&](int c, int s) {
        const uint32_t sbase = sb + (uint32_t)s * STAGE_BYTES;
#pragma unroll
        for (int i = 0; i < 4; ++i) {
            int cid = tid + i * 256;
            int row = cid >> 3;
            int kc  = cid & 7;
            uint32_t so = (uint32_t)(row * LDSTRIDE + kc * 8) * 2;
            size_t ga = (size_t)(rowA0 + row) * D_MODEL + c * BK + kc * 8;
            size_t gb = (size_t)(rowB0 + row) * D_MODEL + c * BK + kc * 8;
            cp16(sbase + 0 * MAT_BYTES + so, Ah + ga);
            cp16(sbase + 1 * MAT_BYTES + so, Al + ga);
            cp16(sbase + 2 * MAT_BYTES + so, Bh + gb);
            cp16(sbase + 3 * MAT_BYTES + so, Bl + gb);
        }
        asm volatile("cp.async.commit_group;" ::: "memory");
    };

    float acc[4][4][4];
#pragma unroll
    for (int mt = 0; mt < 4; ++mt)
#pragma unroll
        for (int nt = 0; nt < 4; ++nt)
#pragma unroll
            for (int i = 0; i < 4; ++i)
                acc[mt][nt][i] = 0.0f;

    const int arow = lane & 15;
    const int acol = (lane >> 4) * 8;
    const int brow = (lane & 7) + ((lane >> 4) << 3);
    const int bcol = ((lane >> 3) & 1) * 8;

    issue(0, 0);

    for (int c = 0; c < NCHUNK; ++c) {
        if (c + 1 < NCHUNK) {
            issue(c + 1, (c + 1) & 1);
            asm volatile("cp.async.wait_group 1;" ::: "memory");
        } else {
            asm volatile("cp.async.wait_group 0;" ::: "memory");
        }
        __syncthreads();

        const uint32_t sbase = sb + (uint32_t)(c & 1) * STAGE_BYTES;
        const uint32_t aH = sbase;
        const uint32_t aL = sbase + 1 * MAT_BYTES;
        const uint32_t bH = sbase + 2 * MAT_BYTES;
        const uint32_t bL = sbase + 3 * MAT_BYTES;

#pragma unroll
        for (int ks = 0; ks < 4; ++ks) {
            const int k0 = ks * 16;
            uint32_t ah[4][4], al[4][4];
#pragma unroll
            for (int mt = 0; mt < 4; ++mt) {
                uint32_t off = (uint32_t)((wm * 64 + mt * 16 + arow) * LDSTRIDE + k0 + acol) * 2;
                ldsm4(ah[mt], aH + off);
                ldsm4(al[mt], aL + off);
            }
            uint32_t bh[2][4], bl[2][4];
#pragma unroll
            for (int bt = 0; bt < 2; ++bt) {
                uint32_t off = (uint32_t)((wn * 32 + bt * 16 + brow) * LDSTRIDE + k0 + bcol) * 2;
                ldsm4(bh[bt], bH + off);
                ldsm4(bl[bt], bL + off);
            }
#pragma unroll
            for (int mt = 0; mt < 4; ++mt)
#pragma unroll
                for (int nt = 0; nt < 4; ++nt) {
                    const uint32_t* B_h = &bh[nt >> 1][(nt & 1) * 2];
                    const uint32_t* B_l = &bl[nt >> 1][(nt & 1) * 2];
                    mma16816(acc[mt][nt], ah[mt], B_h);
                    mma16816(acc[mt][nt], ah[mt], B_l);
                    mma16816(acc[mt][nt], al[mt], B_h);
                }
        }
        __syncthreads();
    }

    const int qr = lane >> 2;
    const int qc = (lane & 3) * 2;
#pragma unroll
    for (int mt = 0; mt < 4; ++mt) {
        const int r0 = rowA0 + wm * 64 + mt * 16 + qr;
#pragma unroll
        for (int nt = 0; nt < 4; ++nt) {
            const int col = rowB0 + wn * 32 + nt * 8 + qc;
            const float b0 = bias[col];
            const float b1 = bias[col + 1];
            float2 v0, v1;
            v0.x = acc[mt][nt][0] + b0;  v0.y = acc[mt][nt][1] + b1;
            v1.x = acc[mt][nt][2] + b0;  v1.y = acc[mt][nt][3] + b1;
            *(float2*)&C[(size_t)r0 * D_MODEL + col]       = v0;
            *(float2*)&C[(size_t)(r0 + 8) * D_MODEL + col] = v1;
        }
    }
}

__global__ __launch_bounds__(256, 1)
void gemm_o_kernel(const __nv_bfloat16* __restrict__ Ah,
                   const __nv_bfloat16* __restrict__ Al,
                   const __nv_bfloat16* __restrict__ Bh,
                   const __nv_bfloat16* __restrict__ Bl,
                   const float* __restrict__ bias,
                   float* __restrict__ C)
{
    extern __shared__ __align__(128) char smem[];
    gemm_body(Ah, Al, Bh, Bl, bias, C, blockIdx.y * BM, blockIdx.x * BN, smem);
}

// ---------------------------------------------------------------------------
// tf32 1-term GEMM (Q and K projections): C = A @ Wt^T + bias
// A = tf32-rounded x [M,K] fp32; Wt = tf32-rounded W^T [N,K] fp32.
// Tile 128x128x64, 256 thr (8 warps 2x4), warp 64x32, m16n8k8 tf32.
// smem row stride 68 floats (272 B): ldmatrix 8-row tiles conflict-free.
// ---------------------------------------------------------------------------
#define TSTR 68
#define TMAT_BYTES (128 * TSTR * 4)     // 34816
#define TSTAGE (2 * TMAT_BYTES)         // 69632
#define TGEMM_SMEM (2 * TSTAGE)         // 139264

__global__ __launch_bounds__(256, 1)
void gemm_qk_tf32(const float* __restrict__ A,
                  const float* __restrict__ Wt0,
                  const float* __restrict__ bq, const float* __restrict__ bk,
                  float* __restrict__ qb, float* __restrict__ kb)
{
    extern __shared__ __align__(128) char smem[];
    const uint32_t sb = smem_u32(smem);
    const int tid  = threadIdx.x;
    const int wid  = tid >> 5;
    const int lane = tid & 31;
    const int wm = wid >> 2;
    const int wn = wid & 3;

    const int which = blockIdx.x >> 3;            // 0 = Q, 1 = K
    const int rowB0 = (blockIdx.x & 7) * BN;
    const int rowA0 = blockIdx.y * BM;
    const float* Wt = Wt0 + (size_t)which * D_MODEL * D_MODEL;
    const float* bias = which ? bk : bq;
    float* C = which ? kb : qb;

    auto issue = [&](int c, int s) {
        const uint32_t sbase = sb + (uint32_t)s * TSTAGE;
#pragma unroll
        for (int i = 0; i < 8; ++i) {
            int cid = tid + i * 256;             // 0..2047
            int row = cid >> 4;
            int kc  = cid & 15;
            uint32_t so = (uint32_t)(row * TSTR + kc * 4) * 4;
            size_t ga = (size_t)(rowA0 + row) * D_MODEL + c * BK + kc * 4;
            size_t gb = (size_t)(rowB0 + row) * D_MODEL + c * BK + kc * 4;
            cp16(sbase + so, A + ga);
            cp16(sbase + TMAT_BYTES + so, Wt + gb);
        }
        asm volatile("cp.async.commit_group;" ::: "memory");
    };

    float acc[4][4][4];
#pragma unroll
    for (int mt = 0; mt < 4; ++mt)
#pragma unroll
        for (int nt = 0; nt < 4; ++nt)
#pragma unroll
            for (int i = 0; i < 4; ++i)
                acc[mt][nt][i] = 0.0f;

    // ldmatrix lane -> (tile, row-in-tile)
    const int lmat = lane >> 3;       // 0..3
    const int lrow = lane & 7;        // 0..7
    const int rofs = (lmat & 1) * 8 + lrow;   // row offset within 16
    const int cofs = (lmat >> 1) * 4;          // float-col offset (k half)

    issue(0, 0);

    for (int c = 0; c < NCHUNK; ++c) {
        if (c + 1 < NCHUNK) {
            issue(c + 1, (c + 1) & 1);
            asm volatile("cp.async.wait_group 1;" ::: "memory");
        } else {
            asm volatile("cp.async.wait_group 0;" ::: "memory");
        }
        __syncthreads();

        const uint32_t aB = sb + (uint32_t)(c & 1) * TSTAGE;
        const uint32_t bB = aB + TMAT_BYTES;

#pragma unroll
        for (int ks = 0; ks < 8; ++ks) {
            const int k0f = ks * 8;
            uint32_t ar[4][4];
#pragma unroll
            for (int mt = 0; mt < 4; ++mt) {
                uint32_t off = (uint32_t)((wm * 64 + mt * 16 + rofs) * TSTR + k0f + cofs) * 4;
                ldsm4(ar[mt], aB + off);   // a0..a3 fragments (tf32 bits)
            }
            uint32_t br[2][4];
#pragma unroll
            for (int np = 0; np < 2; ++np) {
                uint32_t off = (uint32_t)((wn * 32 + np * 16 + rofs) * TSTR + k0f + cofs) * 4;
                ldsm4(br[np], bB + off);   // {b0(nt),b0(nt+1),b1(nt),b1(nt+1)}
            }
#pragma unroll
            for (int mt = 0; mt < 4; ++mt)
#pragma unroll
                for (int nt = 0; nt < 4; ++nt)
                    mma1688_tf32(acc[mt][nt], ar[mt],
                                 br[nt >> 1][nt & 1], br[nt >> 1][2 + (nt & 1)]);
        }
        __syncthreads();
    }

    const int qr = lane >> 2;
    const int qc = (lane & 3) * 2;
#pragma unroll
    for (int mt = 0; mt < 4; ++mt) {
        const int r0 = rowA0 + wm * 64 + mt * 16 + qr;
#pragma unroll
        for (int nt = 0; nt < 4; ++nt) {
            const int col = rowB0 + wn * 32 + nt * 8 + qc;
            const float b0 = bias[col];
            const float b1 = bias[col + 1];
            float2 v0, v1;
            v0.x = acc[mt][nt][0] + b0;  v0.y = acc[mt][nt][1] + b1;
            v1.x = acc[mt][nt][2] + b0;  v1.y = acc[mt][nt][3] + b1;
            *(float2*)&C[(size_t)r0 * D_MODEL + col]       = v0;
            *(float2*)&C[(size_t)(r0 + 8) * D_MODEL + col] = v1;
        }
    }
}

// ---------------------------------------------------------------------------
// Dilated attention v2: lane = neighbor for scores, lane = dim for V-accum.
// Block = (b, h, 32 queries); K/V/Q window staged in smem.
// Fast path requires tmax <= 31 and window rows <= CAP_ROWS.
// ---------------------------------------------------------------------------
#define QTILE 32
#define CAP_ROWS 80
#define ASTR 68                                  // floats per smem row
#define ATT_SMEM ((2 * CAP_ROWS + QTILE) * ASTR * 4 + 8 * 32 * 4)

__global__ __launch_bounds__(256)
void attn_tile_kernel(const float* __restrict__ Q,
                      const float* __restrict__ Kb,
                      const float* __restrict__ V,
                      __nv_bfloat16* __restrict__ Oh,
                      __nv_bfloat16* __restrict__ Ol,
                      const int* __restrict__ kptr,
                      const int* __restrict__ dptr)
{
    extern __shared__ __align__(16) float sm[];
    float* Ks = sm;
    float* Vs = Ks + CAP_ROWS * ASTR;
    float* Qs = Vs + CAP_ROWS * ASTR;
    float* Ps = Qs + QTILE * ASTR;               // 8 warps x 32 floats

    const int tid  = threadIdx.x;
    const int wid  = tid >> 5;
    const int lane = tid & 31;

    const int qt = blockIdx.x & (SEQ / QTILE - 1);
    const int bh = blockIdx.x / (SEQ / QTILE);
    const int h  = bh % NHEADS;
    const int b  = bh / NHEADS;
    const int q0 = qt * QTILE;

    const int kw   = *kptr;
    const int dil  = *dptr;
    const int koff = kw * dil;
    const int tmax = 2 * kw;

    const int base = max(0, q0 - koff);
    const int top  = min(SEQ - 1, q0 + QTILE - 1 + koff);
    const int rows = top - base + 1;
    const bool fast = (rows <= CAP_ROWS) && (tmax <= 31);

    const size_t gbase = (size_t)(b * SEQ) * D_MODEL + h * DHEAD;
    const float scale = rsqrtf((float)DHEAD);

    if (fast) {
        // stage K/V window + Q tile
        const int nchunk = rows * (DHEAD / 4);
        for (int c = tid; c < nchunk; c += 256) {
            const int r = c >> 4, d4 = (c & 15);
            const size_t g = gbase + (size_t)(base + r) * D_MODEL + d4 * 4;
            *(float4*)&Ks[r * ASTR + d4 * 4] = *(const float4*)&Kb[g];
            *(float4*)&Vs[r * ASTR + d4 * 4] = *(const float4*)&V[g];
        }
        for (int c = tid; c < QTILE * (DHEAD / 4); c += 256) {
            const int r = c >> 4, d4 = (c & 15);
            *(float4*)&Qs[r * ASTR + d4 * 4] =
                *(const float4*)&Q[gbase + (size_t)(q0 + r) * D_MODEL + d4 * 4];
        }
        __syncthreads();

        float* Pw = Ps + wid * 32;

#pragma unroll
        for (int qi = 0; qi < 4; ++qi) {
            const int q = q0 + wid * 4 + qi;
            const int r0q = q - koff - base;      // smem row of neighbor t=0

            // ---- phase 1: lane t computes score of neighbor t ----
            const int t = lane;
            const int j = q + (t - kw) * dil;
            const bool act = (t <= tmax) && (j >= 0) && (j < SEQ);
            const int rj = min(max(r0q + t * dil, 0), rows - 1);

            float s = 0.0f;
            const float4* krow = (const float4*)&Ks[rj * ASTR];
            const float4* qrow = (const float4*)&Qs[(q - q0) * ASTR];
#pragma unroll
            for (int d4 = 0; d4 < 16; ++d4) {
                float4 kk = krow[d4];
                float4 qq = qrow[d4];            // lane-uniform broadcast
                s += qq.x * kk.x + qq.y * kk.y + qq.z * kk.z + qq.w * kk.w;
            }
            s = act ? s * scale : -1e30f;

            float mx = s;
#pragma unroll
            for (int o = 16; o > 0; o >>= 1)
                mx = fmaxf(mx, __shfl_xor_sync(0xffffffffu, mx, o));
            float e = act ? __expf(s - mx) : 0.0f;
            float sum = e;
#pragma unroll
            for (int o = 16; o > 0; o >>= 1)
                sum += __shfl_xor_sync(0xffffffffu, sum, o);

            Pw[lane] = e;
            __syncwarp();

            // ---- phase 2: lane owns dims (lane, lane+32) ----
            float a0 = 0.0f, a1 = 0.0f;
            int rj2 = r0q;
            for (int tt = 0; tt <= tmax; ++tt, rj2 += dil) {
                const float p = Pw[tt];
                const int r = min(max(rj2, 0), rows - 1);
                a0 += p * Vs[r * ASTR + lane];
                a1 += p * Vs[r * ASTR + lane + 32];
            }
            __syncwarp();

            const float inv = 1.0f / sum;
            const float o0 = a0 * inv, o1 = a1 * inv;
            const size_t rowq = gbase + (size_t)q * D_MODEL;
            __nv_bfloat16 h0 = __float2bfloat16(o0);
            __nv_bfloat16 h1 = __float2bfloat16(o1);
            Oh[rowq + lane]      = h0;
            Oh[rowq + lane + 32] = h1;
            Ol[rowq + lane]      = __float2bfloat16(o0 - __bfloat162float(h0));
            Ol[rowq + lane + 32] = __float2bfloat16(o1 - __bfloat162float(h1));
        }
        return;
    }

    // ---- fallback: per-neighbor loop straight from gmem (general k/dil) ----
#pragma unroll
    for (int qi = 0; qi < 4; ++qi) {
        const int q = q0 + wid * 4 + qi;
        const size_t rowq = gbase + (size_t)q * D_MODEL;
        const float q0f = Q[rowq + lane];
        const float q1f = Q[rowq + lane + 32];

        float m = -1e30f, l = 0.0f, a0 = 0.0f, a1 = 0.0f;
        for (int t = 0; t <= tmax; ++t) {
            const int j = q + (t - kw) * dil;
            if (j < 0 || j >= SEQ) continue;
            const size_t rowj = gbase + (size_t)j * D_MODEL;
            float p = q0f * Kb[rowj + lane] + q1f * Kb[rowj + lane + 32];
#pragma unroll
            for (int s = 16; s > 0; s >>= 1)
                p += __shfl_xor_sync(0xffffffffu, p, s);
            const float sc = p * scale;
            const float mn   = fmaxf(m, sc);
            const float corr = __expf(m - mn);
            const float e    = __expf(sc - mn);
            a0 = a0 * corr + e * V[rowj + lane];
            a1 = a1 * corr + e * V[rowj + lane + 32];
            l  = l * corr + e;
            m  = mn;
        }
        const float inv = 1.0f / l;
        const float o0 = a0 * inv, o1 = a1 * inv;
        __nv_bfloat16 h0 = __float2bfloat16(o0);
        __nv_bfloat16 h1 = __float2bfloat16(o1);
        Oh[rowq + lane]      = h0;
        Oh[rowq + lane + 32] = h1;
        Ol[rowq + lane]      = __float2bfloat16(o0 - __bfloat162float(h0));
        Ol[rowq + lane + 32] = __float2bfloat16(o1 - __bfloat162float(h1));
    }
}

// ---------------------------------------------------------------------------
// Launch
// ---------------------------------------------------------------------------
extern "C" void kernel_launch(void* const* d_in, const int* in_sizes, int n_in,
                              void* d_out, int out_size)
{
    const float* x  = (const float*)d_in[0];
    const float* Wq = (const float*)d_in[1];
    const float* bq = (const float*)d_in[2];
    const float* Wk = (const float*)d_in[3];
    const float* bk = (const float*)d_in[4];
    const float* Wv = (const float*)d_in[5];
    const float* bv = (const float*)d_in[6];
    const float* Wo = (const float*)d_in[7];
    const float* bo = (const float*)d_in[8];
    const int*   kp = (const int*)d_in[9];
    const int*   dp = (const int*)d_in[10];
    float* out = (float*)d_out;

    void *pq, *pk, *pv, *pxt, *pwt, *pxh, *pxl, *pah, *pal, *pwh, *pwl;
    cudaGetSymbolAddress(&pq,  g_q);
    cudaGetSymbolAddress(&pk,  g_k);
    cudaGetSymbolAddress(&pv,  g_v);
    cudaGetSymbolAddress(&pxt, g_xt);
    cudaGetSymbolAddress(&pwt, g_wt);
    cudaGetSymbolAddress(&pxh, g_xh);
    cudaGetSymbolAddress(&pxl, g_xl);
    cudaGetSymbolAddress(&pah, g_ah);
    cudaGetSymbolAddress(&pal, g_al);
    cudaGetSymbolAddress(&pwh, g_wh);
    cudaGetSymbolAddress(&pwl, g_wl);
    float* qbuf = (float*)pq;
    float* kbuf = (float*)pk;
    float* vbuf = (float*)pv;
    float* xt   = (float*)pxt;
    float* wt   = (float*)pwt;
    __nv_bfloat16* xh = (__nv_bfloat16*)pxh;
    __nv_bfloat16* xl = (__nv_bfloat16*)pxl;
    __nv_bfloat16* ah = (__nv_bfloat16*)pah;
    __nv_bfloat16* al = (__nv_bfloat16*)pal;
    __nv_bfloat16* wh = (__nv_bfloat16*)pwh;
    __nv_bfloat16* wl = (__nv_bfloat16*)pwl;
    const size_t WSZ = (size_t)D_MODEL * D_MODEL;

    cudaFuncSetAttribute(gemm_o_kernel,  cudaFuncAttributeMaxDynamicSharedMemorySize, GEMM_SMEM);
    cudaFuncSetAttribute(gemm_qk_tf32,   cudaFuncAttributeMaxDynamicSharedMemorySize, TGEMM_SMEM);
    cudaFuncSetAttribute(attn_tile_kernel, cudaFuncAttributeMaxDynamicSharedMemorySize, ATT_SMEM);

    // 1) x -> bf16 hi/lo + tf32-rounded
    {
        int n4 = MROWS * D_MODEL / 4;
        split_kernel<<<(n4 + 255) / 256, 256>>>(x, xh, xl, xt, n4);
    }
    // 2) weights: Wq,Wk -> tf32 W^T; Wv,Wo -> bf16 hi/lo W^T
    {
        dim3 tb(32, 8), tg(D_MODEL / 32, D_MODEL / 32, 4);
        wsplit_kernel<<<tg, tb>>>(Wq, Wk, Wv, Wo, wt, wh, wl);
    }
    // 3) Q,K projections: tf32 1-term
    {
        dim3 gg(2 * (D_MODEL / BN), MROWS / BM);   // (16, 64)
        gemm_qk_tf32<<<gg, 256, TGEMM_SMEM>>>(xt, wt, bq, bk, qbuf, kbuf);
    }
    // 4) V projection: bf16 3-term
    {
        dim3 gg(D_MODEL / BN, MROWS / BM);
        gemm_o_kernel<<<gg, 256, GEMM_SMEM>>>(xh, xl, wh + 2 * WSZ, wl + 2 * WSZ, bv, vbuf);
    }
    // 5) dilated attention -> bf16 hi/lo
    {
        const int n_blocks = BATCH * NHEADS * (SEQ / QTILE);   // 4096
        attn_tile_kernel<<<n_blocks, 256, ATT_SMEM>>>(qbuf, kbuf, vbuf, ah, al, kp, dp);
    }
    // 6) output projection -> d_out
    {
        dim3 gg(D_MODEL / BN, MROWS / BM);
        gemm_o_kernel<<<gg, 256, GEMM_SMEM>>>(ah, al, wh + 3 * WSZ, wl + 3 * WSZ, bo, out);
    }
}